// round 4
// baseline (speedup 1.0000x reference)
#include <cuda_runtime.h>
#include <math.h>

#define N_NODES 50000
#define N_EDGES 800000
#define DD 32
#define HH 64
#define L_LAYERS 4
#define SPR 264          // padded smem row stride for 256-edge tiles (floats)

typedef unsigned long long ull;

// ---------------- scratch ----------------
__device__ float g_h[(size_t)N_NODES * DD];
__device__ float g_e[L_LAYERS + 1][(size_t)N_EDGES * DD];
__device__ float g_agg[(size_t)N_NODES * DD];

// ---------------- packed fp32x2 helpers ----------------
__device__ __forceinline__ ull pack2(float a, float b) {
    ull r; asm("mov.b64 %0,{%1,%2};" : "=l"(r) : "f"(a), "f"(b)); return r;
}
__device__ __forceinline__ float2 unpack2(ull v) {
    float2 r; asm("mov.b64 {%0,%1},%2;" : "=f"(r.x), "=f"(r.y) : "l"(v)); return r;
}
__device__ __forceinline__ void fma2(ull& d, ull a, ull b) {
    asm("fma.rn.f32x2 %0,%1,%2,%0;" : "+l"(d) : "l"(a), "l"(b));
}
__device__ __forceinline__ void red_add_v2(float* p, float x, float y) {
    asm volatile("red.global.add.v2.f32 [%0], {%1,%2};" :: "l"(p), "f"(x), "f"(y) : "memory");
}

__device__ __forceinline__ void coop_load(float* dst, const float* src, int n, int t, int nt) {
    for (int i = t; i < n; i += nt) dst[i] = src[i];
}

// store a float4 down a column of the transposed activation tile
__device__ __forceinline__ void st4col(float* smT, int row, int e, float4 v) {
    smT[(row + 0) * SPR + e] = v.x;
    smT[(row + 1) * SPR + e] = v.y;
    smT[(row + 2) * SPR + e] = v.z;
    smT[(row + 3) * SPR + e] = v.w;
}

// 4-edge x (2*NU)-out register-tile FMA step
template <int NU>
__device__ __forceinline__ void tile_fma(float4 a, const ull* __restrict__ wp, ull acc[4][NU]) {
    ull w[NU];
#pragma unroll
    for (int j = 0; j < NU; j++) w[j] = wp[j];
    ull a0 = pack2(a.x, a.x), a1 = pack2(a.y, a.y), a2 = pack2(a.z, a.z), a3 = pack2(a.w, a.w);
#pragma unroll
    for (int j = 0; j < NU; j++) {
        fma2(acc[0][j], a0, w[j]);
        fma2(acc[1][j], a1, w[j]);
        fma2(acc[2][j], a2, w[j]);
        fma2(acc[3][j], a3, w[j]);
    }
}

template <int NU>
__device__ __forceinline__ void init_bias(ull acc[4][NU], const float* b, int base) {
#pragma unroll
    for (int j = 0; j < NU; j++) {
        ull bj = pack2(b[base + 2 * j], b[base + 2 * j + 1]);
#pragma unroll
        for (int i = 0; i < 4; i++) acc[i][j] = bj;
    }
}
template <int NU>
__device__ __forceinline__ void init_zero_t(ull acc[4][NU]) {
#pragma unroll
    for (int j = 0; j < NU; j++)
#pragma unroll
        for (int i = 0; i < 4; i++) acc[i][j] = 0ull;
}

__device__ __forceinline__ float relu_sel(ull v, int hi) {
    float2 f = unpack2(v); return fmaxf(hi ? f.y : f.x, 0.f);
}

// relu(acc 4x16) -> transposed rows [og*16..og*16+15], cols [4eg..4eg+3], via STS.128
__device__ __forceinline__ void relu_writeT16(float* smT, ull acc[4][8], int og, int eg) {
#pragma unroll
    for (int cc = 0; cc < 16; cc++) {
        int j = cc >> 1, hi = cc & 1;
        float4 v;
        v.x = relu_sel(acc[0][j], hi);
        v.y = relu_sel(acc[1][j], hi);
        v.z = relu_sel(acc[2][j], hi);
        v.w = relu_sel(acc[3][j], hi);
        *(float4*)&smT[(og * 16 + cc) * SPR + 4 * eg] = v;
    }
}

// K-step GEMM loop: acc += smT[k][4eg..] * W[k][wo..]
template <int K, int NU>
__device__ __forceinline__ void mma_loop(const float* smT, const float* W, int wld, int wo,
                                         int eg, ull acc[4][NU]) {
#pragma unroll 2
    for (int k = 0; k < K; k++) {
        float4 a = *(const float4*)&smT[k * SPR + 4 * eg];
        tile_fma<NU>(a, (const ull*)&W[k * wld + wo], acc);
    }
}

// ---------------- per-thread helpers (node encoder only) ----------------
template <int OUTP>
__device__ __forceinline__ void consume1(float a, const float* Wrow, ull* acc) {
    ull a2 = pack2(a, a);
    const ull* w = reinterpret_cast<const ull*>(Wrow);
#pragma unroll
    for (int j = 0; j < OUTP; j++) fma2(acc[j], a2, w[j]);
}
template <int OUTP>
__device__ __forceinline__ void init_zero(ull* acc) {
#pragma unroll
    for (int j = 0; j < OUTP; j++) acc[j] = 0ull;
}
template <int OUTP>
__device__ __forceinline__ void relu_store(const ull* acc, ull* s) {
#pragma unroll
    for (int j = 0; j < OUTP; j++) {
        float2 v = unpack2(acc[j]);
        s[j * 128] = pack2(fmaxf(v.x, 0.f), fmaxf(v.y, 0.f));
    }
}
template <int INP, int OUTP>
__device__ __forceinline__ void mlp_scratch(const ull* s, const float* W, ull* acc) {
#pragma unroll 1
    for (int p = 0; p < INP; p++) {
        float2 av = unpack2(s[p * 128]);
        consume1<OUTP>(av.x, W + (size_t)(2 * p) * (2 * OUTP), acc);
        consume1<OUTP>(av.y, W + (size_t)(2 * p + 1) * (2 * OUTP), acc);
    }
}

// ---------------- node encoder (small, per-thread) ----------------
__global__ __launch_bounds__(128) void node_enc_kernel(const float* __restrict__ x,
                                                       const float* __restrict__ W1,
                                                       const float* __restrict__ W2) {
    extern __shared__ float sm[];
    float* sW1 = sm;                 // 896
    float* sW2 = sm + 896;           // 2048
    ull* scr = (ull*)(sm + 2944);
    int t = threadIdx.x;
    coop_load(sW1, W1, 896, t, 128);
    coop_load(sW2, W2, 2048, t, 128);
    __syncthreads();
    int n = blockIdx.x * 128 + t;
    if (n >= N_NODES) return;
    const float* xr = x + (size_t)n * 14;
    ull acc[32]; init_zero<32>(acc);
#pragma unroll 1
    for (int k = 0; k < 14; k++) consume1<32>(xr[k], sW1 + k * 64, acc);
    relu_store<32>(acc, scr + t);
    ull acc2[16]; init_zero<16>(acc2);
    mlp_scratch<32, 16>(scr + t, sW2, acc2);
    float4* ho = (float4*)(g_h + (size_t)n * DD);
#pragma unroll
    for (int q = 0; q < 8; q++) {
        float2 v0 = unpack2(acc2[2 * q]);
        float2 v1 = unpack2(acc2[2 * q + 1]);
        float4 o;
        o.x = fmaxf(v0.x, 0.f); o.y = fmaxf(v0.y, 0.f);
        o.z = fmaxf(v1.x, 0.f); o.w = fmaxf(v1.y, 0.f);
        ho[q] = o;
    }
}

// ---------------- tiled edge encoder: ea[E,4] -> e0[E,32] ----------------
// 256 edges / 256 threads per block
__global__ __launch_bounds__(256, 2) void edge_enc_tile_kernel(const float* __restrict__ ea,
                                                               const float* __restrict__ W1,
                                                               const float* __restrict__ W2) {
    extern __shared__ float sm[];
    float* sW1 = sm;                 // 4*64 = 256
    float* sW2 = sm + 256;           // 64*32 = 2048
    float* smT = sm + 2304;          // 64*SPR
    int t = threadIdx.x;
    coop_load(sW1, W1, 256, t, 256);
    coop_load(sW2, W2, 2048, t, 256);
    int blk = blockIdx.x * 256;
    {
        float4 av = ((const float4*)ea)[blk + t];
        st4col(smT, 0, t, av);
    }
    __syncthreads();
    int eg = t & 63, og = t >> 6;    // 4 edges x 16 outs
    ull acc[4][8];
    init_zero_t<8>(acc);
    mma_loop<4, 8>(smT, sW1, 64, og * 16, eg, acc);
    __syncthreads();
    relu_writeT16(smT, acc, og, eg);
    __syncthreads();
    // layer 2: 64 -> 32, tile 4 x 8
    ull acc3[4][4];
    init_zero_t<4>(acc3);
    mma_loop<64, 4>(smT, sW2, 32, og * 8, eg, acc3);
#pragma unroll
    for (int i = 0; i < 4; i++) {
        int eid_i = blk + 4 * eg + i;
#pragma unroll
        for (int j = 0; j < 4; j++) {
            int c = og * 8 + 2 * j;
            float2 v = unpack2(acc3[i][j]);
            float2 o; o.x = fmaxf(v.x, 0.f); o.y = fmaxf(v.y, 0.f);
            *(float2*)&g_e[0][(size_t)eid_i * DD + c] = o;
        }
    }
}

// ---------------- tiled relational kernel ----------------
// 256 edges / 256 threads. smT[96][SPR]. thread tile = 4 edges x 16 outs.
__global__ __launch_bounds__(256, 1) void rel_tile_kernel(const int* __restrict__ ei, int layer,
        const float* __restrict__ W1, const float* __restrict__ b1,
        const float* __restrict__ W2, const float* __restrict__ b2,
        const float* __restrict__ W3, const float* __restrict__ b3) {
    extern __shared__ float sm[];
    float* sW1 = sm;                    // 6144
    float* sW2 = sm + 6144;             // 4096
    float* sW3 = sm + 10240;            // 2048
    float* sb1 = sm + 12288;            // 64
    float* sb2 = sm + 12352;            // 64
    float* sb3 = sm + 12416;            // 32
    float* smT = sm + 12448;            // 96*SPR (16B aligned)
    int*   sdst = (int*)(sm + 12448 + 96 * SPR);  // 256

    int t = threadIdx.x;
    coop_load(sW1, W1, 6144, t, 256);
    coop_load(sW2, W2, 4096, t, 256);
    coop_load(sW3, W3, 2048, t, 256);
    coop_load(sb1, b1, 64, t, 256);
    coop_load(sb2, b2, 64, t, 256);
    coop_load(sb3, b3, 32, t, 256);

    const float* e_in = g_e[layer];
    float* e_out = g_e[layer + 1];
    int blk = blockIdx.x * 256;

    // ---- gather/fill transposed activations (1 edge per thread) ----
    {
        int eid = blk + t;
        int s = ei[eid];
        int d = ei[N_EDGES + eid];
        sdst[t] = d;
        const float4* hd = (const float4*)(g_h + (size_t)d * DD);
        const float4* hs = (const float4*)(g_h + (size_t)s * DD);
        const float4* ep = (const float4*)(e_in + (size_t)eid * DD);
#pragma unroll
        for (int q = 0; q < 8; q++) st4col(smT, 4 * q, t, hd[q]);
#pragma unroll
        for (int q = 0; q < 8; q++) st4col(smT, 32 + 4 * q, t, hs[q]);
#pragma unroll
        for (int q = 0; q < 8; q++) st4col(smT, 64 + 4 * q, t, ep[q]);
    }
    __syncthreads();

    int eg = t & 63;       // edges 4eg..4eg+3
    int og = t >> 6;       // outs 16og..16og+15

    // ---- layer 1: 96 -> 64 ----
    ull acc[4][8];
    init_bias<8>(acc, sb1, og * 16);
    mma_loop<96, 8>(smT, sW1, 64, og * 16, eg, acc);
    __syncthreads();
    relu_writeT16(smT, acc, og, eg);
    __syncthreads();

    // ---- layer 2: 64 -> 64 ----
    init_bias<8>(acc, sb2, og * 16);
    mma_loop<64, 8>(smT, sW2, 64, og * 16, eg, acc);
    __syncthreads();
    relu_writeT16(smT, acc, og, eg);
    __syncthreads();

    // ---- layer 3: 64 -> 32 (tile 4 x 8) ----
    ull acc3[4][4];
    init_bias<4>(acc3, sb3, og * 8);
    mma_loop<64, 4>(smT, sW3, 32, og * 8, eg, acc3);

    // ---- epilogue: residual e_out, vector red agg ----
#pragma unroll
    for (int i = 0; i < 4; i++) {
        int e_i = 4 * eg + i;
        int eid_i = blk + e_i;
        int d_i = sdst[e_i];
#pragma unroll
        for (int j = 0; j < 4; j++) {
            int c = og * 8 + 2 * j;
            float2 v = unpack2(acc3[i][j]);
            float ein0 = smT[(64 + c) * SPR + e_i];
            float ein1 = smT[(64 + c + 1) * SPR + e_i];
            float2 o;
            o.x = 0.5f * ein0 + 0.5f * v.x;
            o.y = 0.5f * ein1 + 0.5f * v.y;
            *(float2*)&e_out[(size_t)eid_i * DD + c] = o;
            red_add_v2(&g_agg[(size_t)d_i * DD + c], v.x, v.y);
        }
    }
}

// ---------------- tiled object kernel: h = 0.5h + 0.5*MLP3([h, agg]) ----------------
// 256 nodes / 256 threads. smT[64][SPR]. column-separable so ragged tail is safe.
__global__ __launch_bounds__(256, 2) void obj_tile_kernel(const float* __restrict__ W1, const float* __restrict__ b1,
        const float* __restrict__ W2, const float* __restrict__ b2,
        const float* __restrict__ W3, const float* __restrict__ b3) {
    extern __shared__ float sm[];
    float* sW1 = sm;                 // 4096
    float* sW2 = sm + 4096;          // 4096
    float* sW3 = sm + 8192;          // 2048
    float* sb1 = sm + 10240;
    float* sb2 = sm + 10304;
    float* sb3 = sm + 10368;
    float* smT = sm + 10400;         // 64*SPR (byte 41600, 16B aligned)

    int t = threadIdx.x;
    coop_load(sW1, W1, 4096, t, 256);
    coop_load(sW2, W2, 4096, t, 256);
    coop_load(sW3, W3, 2048, t, 256);
    coop_load(sb1, b1, 64, t, 256);
    coop_load(sb2, b2, 64, t, 256);
    coop_load(sb3, b3, 32, t, 256);

    int blk = blockIdx.x * 256;
    {
        int n = blk + t;
        if (n < N_NODES) {
            const float4* hp = (const float4*)(g_h + (size_t)n * DD);
            const float4* ap = (const float4*)(g_agg + (size_t)n * DD);
#pragma unroll
            for (int q = 0; q < 8; q++) st4col(smT, 4 * q, t, hp[q]);
#pragma unroll
            for (int q = 0; q < 8; q++) st4col(smT, 32 + 4 * q, t, ap[q]);
        }
    }
    __syncthreads();

    int eg = t & 63, og = t >> 6;

    ull acc[4][8];
    init_bias<8>(acc, sb1, og * 16);
    mma_loop<64, 8>(smT, sW1, 64, og * 16, eg, acc);
    __syncthreads();
    relu_writeT16(smT, acc, og, eg);
    __syncthreads();

    init_bias<8>(acc, sb2, og * 16);
    mma_loop<64, 8>(smT, sW2, 64, og * 16, eg, acc);
    __syncthreads();
    relu_writeT16(smT, acc, og, eg);
    __syncthreads();

    ull acc3[4][4];
    init_bias<4>(acc3, sb3, og * 8);
    mma_loop<64, 4>(smT, sW3, 32, og * 8, eg, acc3);

#pragma unroll
    for (int i = 0; i < 4; i++) {
        int n_i = blk + 4 * eg + i;
        if (n_i < N_NODES) {
#pragma unroll
            for (int j = 0; j < 4; j++) {
                int c = og * 8 + 2 * j;
                float2 v = unpack2(acc3[i][j]);
                float2 hold = *(float2*)&g_h[(size_t)n_i * DD + c];
                float2 o;
                o.x = 0.5f * hold.x + 0.5f * v.x;
                o.y = 0.5f * hold.y + 0.5f * v.y;
                *(float2*)&g_h[(size_t)n_i * DD + c] = o;
            }
        }
    }
}

// ---------------- tiled final edge scorer ----------------
// w_in = [h_src, h_dst, e1..e4] (192) -> 64 -> 64 -> 1, two-pass W1 staging
__global__ __launch_bounds__(256, 1) void final_tile_kernel(const int* __restrict__ ei,
        const float* __restrict__ W1, const float* __restrict__ b1,
        const float* __restrict__ W2, const float* __restrict__ b2,
        const float* __restrict__ W3, const float* __restrict__ b3,
        float* __restrict__ out) {
    extern __shared__ float sm[];
    float* sW1 = sm;                    // 6144 (staged half of 192x64)
    float* sW2 = sm + 6144;             // 4096
    float* sW3 = sm + 10240;            // 64
    float* sb1 = sm + 10304;            // 64
    float* sb2 = sm + 10368;            // 64
    float* sb3 = sm + 10432;            // 1 (+3 pad)
    float* smT = sm + 10436;            // 96*SPR (byte 41744, 16B aligned)

    int t = threadIdx.x;
    coop_load(sW1, W1, 6144, t, 256);
    coop_load(sW2, W2, 4096, t, 256);
    coop_load(sW3, W3, 64, t, 256);
    coop_load(sb1, b1, 64, t, 256);
    coop_load(sb2, b2, 64, t, 256);
    if (t == 0) sb3[0] = b3[0];

    int blk = blockIdx.x * 256;
    int eid = blk + t;
    int s = ei[eid];
    int d = ei[N_EDGES + eid];

    // ---- pass A fill: h_src(0..31), h_dst(32..63), e1(64..95) ----
    {
        const float4* hs = (const float4*)(g_h + (size_t)s * DD);
        const float4* hd = (const float4*)(g_h + (size_t)d * DD);
        const float4* e1 = (const float4*)(g_e[1] + (size_t)eid * DD);
#pragma unroll
        for (int q = 0; q < 8; q++) st4col(smT, 4 * q, t, hs[q]);
#pragma unroll
        for (int q = 0; q < 8; q++) st4col(smT, 32 + 4 * q, t, hd[q]);
#pragma unroll
        for (int q = 0; q < 8; q++) st4col(smT, 64 + 4 * q, t, e1[q]);
    }
    __syncthreads();

    int eg = t & 63, og = t >> 6;
    ull acc[4][8];
    init_bias<8>(acc, sb1, og * 16);
    mma_loop<96, 8>(smT, sW1, 64, og * 16, eg, acc);
    __syncthreads();

    // ---- pass B fill: e2(0..31), e3(32..63), e4(64..95) + W1 rows 96..191 ----
    {
        const float4* e2 = (const float4*)(g_e[2] + (size_t)eid * DD);
        const float4* e3 = (const float4*)(g_e[3] + (size_t)eid * DD);
        const float4* e4 = (const float4*)(g_e[4] + (size_t)eid * DD);
#pragma unroll
        for (int q = 0; q < 8; q++) st4col(smT, 4 * q, t, e2[q]);
#pragma unroll
        for (int q = 0; q < 8; q++) st4col(smT, 32 + 4 * q, t, e3[q]);
#pragma unroll
        for (int q = 0; q < 8; q++) st4col(smT, 64 + 4 * q, t, e4[q]);
    }
    coop_load(sW1, W1 + 96 * 64, 6144, t, 256);
    __syncthreads();

    mma_loop<96, 8>(smT, sW1, 64, og * 16, eg, acc);
    __syncthreads();
    relu_writeT16(smT, acc, og, eg);
    __syncthreads();

    // ---- layer 2: 64 -> 64 ----
    init_bias<8>(acc, sb2, og * 16);
    mma_loop<64, 8>(smT, sW2, 64, og * 16, eg, acc);
    __syncthreads();
    relu_writeT16(smT, acc, og, eg);
    __syncthreads();

    // ---- layer 3: dot(64) -> sigmoid (1 edge per thread) ----
    {
        float logit = sb3[0];
#pragma unroll 2
        for (int k = 0; k < 64; k++) logit += smT[k * SPR + t] * sW3[k];
        float sig = 1.f / (1.f + expf(-logit));
        out[eid] = 1e-3f + (1.f - 2e-3f) * sig;
    }
}

// ---------------- utility ----------------
__global__ void zero_agg_kernel() {
    int i = blockIdx.x * 256 + threadIdx.x;
    if (i < N_NODES * DD) g_agg[i] = 0.f;
}

__global__ void writeback_kernel(float* __restrict__ out) {
    size_t i = (size_t)blockIdx.x * 256 + threadIdx.x;
    if (i < (size_t)N_NODES * DD) out[(size_t)N_EDGES + i] = g_h[i];
    if (i < (size_t)N_EDGES * DD) out[(size_t)N_EDGES + (size_t)N_NODES * DD + i] = g_e[4][i];
}

// ---------------- launch ----------------
extern "C" void kernel_launch(void* const* d_in, const int* in_sizes, int n_in,
                              void* d_out, int out_size) {
    const float* x      = (const float*)d_in[0];
    const int*   ei     = (const int*)d_in[1];
    const float* ea     = (const float*)d_in[2];
    const float* enW1   = (const float*)d_in[3];
    const float* enW2   = (const float*)d_in[4];
    const float* eeW1   = (const float*)d_in[5];
    const float* eeW2   = (const float*)d_in[6];
    const float* rW1    = (const float*)d_in[7];
    const float* rb1    = (const float*)d_in[8];
    const float* rW2    = (const float*)d_in[9];
    const float* rb2    = (const float*)d_in[10];
    const float* rW3    = (const float*)d_in[11];
    const float* rb3    = (const float*)d_in[12];
    const float* oW1    = (const float*)d_in[13];
    const float* ob1    = (const float*)d_in[14];
    const float* oW2    = (const float*)d_in[15];
    const float* ob2    = (const float*)d_in[16];
    const float* oW3    = (const float*)d_in[17];
    const float* ob3    = (const float*)d_in[18];
    const float* wW1    = (const float*)d_in[19];
    const float* wb1    = (const float*)d_in[20];
    const float* wW2    = (const float*)d_in[21];
    const float* wb2    = (const float*)d_in[22];
    const float* wW3    = (const float*)d_in[23];
    const float* wb3    = (const float*)d_in[24];
    float* out = (float*)d_out;

    const int NODE_SMEM = 2944 * 4 + 128 * 32 * 8;                 // 44544
    const int EE_SMEM   = (2304 + 64 * SPR) * 4;                   // 76800
    const int REL_SMEM  = (12448 + 96 * SPR) * 4 + 256 * 4;        // 152192
    const int OBJ_SMEM  = (10400 + 64 * SPR) * 4;                  // 109184
    const int FIN_SMEM  = (10436 + 96 * SPR) * 4;                  // 143120

    cudaFuncSetAttribute(node_enc_kernel, cudaFuncAttributeMaxDynamicSharedMemorySize, NODE_SMEM);
    cudaFuncSetAttribute(edge_enc_tile_kernel, cudaFuncAttributeMaxDynamicSharedMemorySize, EE_SMEM);
    cudaFuncSetAttribute(rel_tile_kernel, cudaFuncAttributeMaxDynamicSharedMemorySize, REL_SMEM);
    cudaFuncSetAttribute(obj_tile_kernel, cudaFuncAttributeMaxDynamicSharedMemorySize, OBJ_SMEM);
    cudaFuncSetAttribute(final_tile_kernel, cudaFuncAttributeMaxDynamicSharedMemorySize, FIN_SMEM);

    int nodeBlocks = (N_NODES + 127) / 128;        // 391
    int objBlocks  = (N_NODES + 255) / 256;        // 196
    int tileBlocks = N_EDGES / 256;                // 3125 exact

    node_enc_kernel<<<nodeBlocks, 128, NODE_SMEM>>>(x, enW1, enW2);
    edge_enc_tile_kernel<<<tileBlocks, 256, EE_SMEM>>>(ea, eeW1, eeW2);

    for (int l = 0; l < L_LAYERS; l++) {
        zero_agg_kernel<<<(N_NODES * DD + 255) / 256, 256>>>();
        rel_tile_kernel<<<tileBlocks, 256, REL_SMEM>>>(ei, l,
            rW1 + (size_t)l * 96 * 64, rb1 + (size_t)l * 64,
            rW2 + (size_t)l * 64 * 64, rb2 + (size_t)l * 64,
            rW3 + (size_t)l * 64 * 32, rb3 + (size_t)l * 32);
        obj_tile_kernel<<<objBlocks, 256, OBJ_SMEM>>>(
            oW1 + (size_t)l * 64 * 64, ob1 + (size_t)l * 64,
            oW2 + (size_t)l * 64 * 64, ob2 + (size_t)l * 64,
            oW3 + (size_t)l * 64 * 32, ob3 + (size_t)l * 32);
    }

    final_tile_kernel<<<tileBlocks, 256, FIN_SMEM>>>(ei, wW1, wb1, wW2, wb2, wW3, wb3, out);

    writeback_kernel<<<((size_t)N_EDGES * DD + 255) / 256, 256>>>(out);
}